// round 6
// baseline (speedup 1.0000x reference)
#include <cuda_runtime.h>
#include <math.h>

typedef unsigned long long ull;

// ---------------------------------------------------------------------------
// Scratch (static device globals; no runtime allocation)
// ---------------------------------------------------------------------------
__device__ float g_sb[4 * 8 * 64 * 64 * 64];        // subbands [sub][b][c][64][64]
__device__ float g_co[4 * 8 * 64 * 64 * 64];        // conv outs [sub][b][co][64][64]
__device__ float g_sums[8 * 64 * 4];                // per (b,c,sub) sums
__device__ float g_att[8 * 4 * 4];                  // attention [b][sub][k]
__device__ float g_mku[8 * 4 * 16 * 64 * 64];       // Winograd U [b][sub][t][ci][co]

#define SB_STRIDE  2097152
#define NBC        512

// Winograd constant tables (B^T row/col combination selectors, A^T coeffs)
__constant__ int   c_ra[4] = {0, 1, 2, 1};
__constant__ int   c_rb[4] = {2, 2, 1, 3};
__constant__ float c_rs[4] = {-1.f, 1.f, -1.f, -1.f};
__constant__ float c_A0[4] = {1.f, 1.f, 1.f, 0.f};   // A^T row 0
__constant__ float c_A1[4] = {0.f, 1.f, -1.f, -1.f}; // A^T row 1

#define FMA2(acc, a, b) asm volatile("fma.rn.f32x2 %0, %1, %2, %0;" \
                                     : "+l"(acc) : "l"(a), "l"(b))
#define DUP2(dst, v)    asm("mov.b64 %0, {%1, %1};" : "=l"(dst) : "f"(v))

// ---------------------------------------------------------------------------
// Kernel 1: Haar DWT fused with per-(b,c) subband sums
// ---------------------------------------------------------------------------
__global__ void dwt_kernel(const float* __restrict__ x) {
    int bc  = blockIdx.x;
    int tid = threadIdx.x;
    int ow  = tid & 63;
    int oh0 = tid >> 6;
    const float* xp = x + (size_t)bc * 128 * 128;

    float s0 = 0.f, s1 = 0.f, s2 = 0.f, s3 = 0.f;
    #pragma unroll 4
    for (int it = 0; it < 16; ++it) {
        int oh = oh0 + it * 4;
        float2 t  = ((const float2*)(xp + (2 * oh)     * 128))[ow];
        float2 bo = ((const float2*)(xp + (2 * oh + 1) * 128))[ow];
        float a = t.x, b_ = t.y, c_ = bo.x, d_ = bo.y;
        float ll = (a + b_ + c_ + d_) * 0.5f;
        float h0 = (a + b_ - c_ - d_) * 0.5f;
        float h1 = (a - b_ + c_ - d_) * 0.5f;
        float hh = (a - b_ - c_ + d_) * 0.5f;
        int o = bc * 4096 + oh * 64 + ow;
        g_sb[0 * SB_STRIDE + o] = ll;
        g_sb[1 * SB_STRIDE + o] = h0;
        g_sb[2 * SB_STRIDE + o] = h1;
        g_sb[3 * SB_STRIDE + o] = hh;
        s0 += ll; s1 += h0; s2 += h1; s3 += hh;
    }

    #pragma unroll
    for (int off = 16; off; off >>= 1) {
        s0 += __shfl_down_sync(0xffffffffu, s0, off);
        s1 += __shfl_down_sync(0xffffffffu, s1, off);
        s2 += __shfl_down_sync(0xffffffffu, s2, off);
        s3 += __shfl_down_sync(0xffffffffu, s3, off);
    }
    __shared__ float red[8][4];
    int warp = tid >> 5, lane = tid & 31;
    if (lane == 0) {
        red[warp][0] = s0; red[warp][1] = s1;
        red[warp][2] = s2; red[warp][3] = s3;
    }
    __syncthreads();
    if (tid < 4) {
        float s = 0.f;
        #pragma unroll
        for (int w = 0; w < 8; ++w) s += red[w][tid];
        g_sums[bc * 4 + tid] = s;
    }
}

// ---------------------------------------------------------------------------
// Kernel 2a: attention logits + softmax
// ---------------------------------------------------------------------------
__global__ void attn_kernel(const float* __restrict__ attn_w,
                            const float* __restrict__ attn_b) {
    int t = threadIdx.x;
    if (t >= 32) return;
    int b = t >> 2, i = t & 3;
    float logits[4];
    #pragma unroll
    for (int k = 0; k < 4; ++k) {
        float acc = 0.f;
        for (int c = 0; c < 64; ++c)
            acc += attn_w[k * 64 + c] * g_sums[(b * 64 + c) * 4 + i];
        logits[k] = acc * (1.0f / 4096.0f) + attn_b[k];
    }
    float m = fmaxf(fmaxf(logits[0], logits[1]), fmaxf(logits[2], logits[3]));
    float e[4]; float s = 0.f;
    #pragma unroll
    for (int k = 0; k < 4; ++k) { e[k] = expf(logits[k] - m); s += e[k]; }
    float inv = 1.0f / s;
    #pragma unroll
    for (int k = 0; k < 4; ++k) g_att[(b * 4 + i) * 4 + k] = e[k] * inv;
}

// ---------------------------------------------------------------------------
// Kernel 2b: mix kernels with attention AND transform to Winograd U.
//   U[b][i][t=(r*4+cl)][ci][co] = (G g Gt)[r][cl],  g = sum_k att * wt[k][i]
// Block: (cig of 4 ci, i, b). Thread: (cil = tid>>6, co = tid&63).
// ---------------------------------------------------------------------------
__global__ void wino_mix(const float* __restrict__ wt) {
    int cig = blockIdx.x, i = blockIdx.y, b = blockIdx.z;
    int bi = b * 4 + i;
    __shared__ float s[36 * 65];

    int tid = threadIdx.x;
    int co  = tid & 63;
    int cil = tid >> 6;

    float g9[9];
    #pragma unroll
    for (int q = 0; q < 9; ++q) g9[q] = 0.f;

    #pragma unroll
    for (int k = 0; k < 4; ++k) {
        float ak = g_att[bi * 4 + k];
        const float* src = wt + ((size_t)(k * 4 + i) * 64) * 576 + cig * 36;
        __syncthreads();
        for (int idx = tid; idx < 64 * 36; idx += 256) {
            int c = idx / 36;
            int j = idx - c * 36;
            s[j * 65 + c] = src[(size_t)c * 576 + j];
        }
        __syncthreads();
        #pragma unroll
        for (int q = 0; q < 9; ++q)
            g9[q] += ak * s[(cil * 9 + q) * 65 + co];
    }

    // U = G g G^T ; G = [[1,0,0],[.5,.5,.5],[.5,-.5,.5],[0,0,1]]
    float T[4][3];
    #pragma unroll
    for (int c = 0; c < 3; ++c) {
        float a = g9[c], bb = g9[3 + c], cc = g9[6 + c];
        T[0][c] = a;
        T[1][c] = 0.5f * (a + bb + cc);
        T[2][c] = 0.5f * (a - bb + cc);
        T[3][c] = cc;
    }
    float* dst = g_mku + ((size_t)bi * 16) * 4096 + (cig * 4 + cil) * 64 + co;
    #pragma unroll
    for (int r = 0; r < 4; ++r) {
        float u0 = T[r][0], u1b = T[r][1], u2 = T[r][2];
        float U0 = u0;
        float U1 = 0.5f * (u0 + u1b + u2);
        float U2 = 0.5f * (u0 - u1b + u2);
        float U3 = u2;
        dst[(r * 4 + 0) * 4096] = U0;
        dst[(r * 4 + 1) * 4096] = U1;
        dst[(r * 4 + 2) * 4096] = U2;
        dst[(r * 4 + 3) * 4096] = U3;
    }
}

// ---------------------------------------------------------------------------
// Kernel 3: fused Winograd F(2x2,3x3) dynamic conv.
// Block = 256 threads, covers 64 cout x 32 tiles (8x16 output px) of one (b,sub).
// smem: raw halo 64ci x 10 x 18 + 4 V buffers (one per j) 64ci x 32tiles.
// Thread: cog = tid&15 (co4), tpg = tid>>4 (tile pair). 16 ull O-accumulators.
// U read via __ldg (L1/L2 resident).
// ---------------------------------------------------------------------------
__global__ void __launch_bounds__(256, 2) wino_conv() {
    extern __shared__ float sm[];
    float* raw_s = sm;            // 11520 floats
    float* v_s   = sm + 11520;    // 4 * 2048 floats

    int b   = blockIdx.z;
    int sub = blockIdx.y;
    int tb  = blockIdx.x;               // 0..31
    int th0 = (tb >> 2) * 8;            // output row origin
    int tw0 = (tb & 3) * 16;            // output col origin
    int bi  = b * 4 + sub;

    int tid = threadIdx.x;
    int cog = tid & 15;                 // co4 = cog*4
    int tp  = (tid >> 4) * 2;           // tile pair base (0..30)

    const float* sbp = g_sb + (size_t)(sub * 8 + b) * 64 * 4096;

    // ---- stage raw halo: 64 ci x 10 x 18 (zero padded) ----
    for (int idx = tid; idx < 11520; idx += 256) {
        int ci  = idx / 180;
        int rem = idx - ci * 180;
        int y   = rem / 18;
        int xx  = rem - y * 18;
        int ih  = th0 - 1 + y;
        int iw  = tw0 - 1 + xx;
        float v = 0.f;
        if ((unsigned)ih < 64u && (unsigned)iw < 64u)
            v = sbp[ci * 4096 + ih * 64 + iw];
        raw_s[idx] = v;
    }

    ull oacc[2][2][2][2];   // [co-pair p][tile l][out row r][out col c]
    #pragma unroll
    for (int p = 0; p < 2; ++p)
        #pragma unroll
        for (int l = 0; l < 2; ++l)
            #pragma unroll
            for (int r = 0; r < 2; ++r)
                #pragma unroll
                for (int c = 0; c < 2; ++c) oacc[p][l][r][c] = 0ull;

    const float* ubase = g_mku + (size_t)bi * 16 * 4096;

    for (int ig = 0; ig < 4; ++ig) {    // B^T row-combination group (i index)
        int   ra = c_ra[ig] * 18;
        int   rb = c_rb[ig] * 18;
        float rs = c_rs[ig];

        __syncthreads();                // previous group's GEMM done reading v_s
        // ---- transform: V[i=ig][j=0..3] for all (ci, tile) ----
        #pragma unroll
        for (int q = 0; q < 8; ++q) {
            int idx = tid + q * 256;    // 2048 cells
            int ci  = idx >> 5;
            int tl  = idx & 31;
            const float* dp = &raw_s[ci * 180 + (tl >> 3) * 36 + (tl & 7) * 2];
            float2 A0 = *(const float2*)(dp + ra);
            float2 A1 = *(const float2*)(dp + ra + 2);
            float2 B0 = *(const float2*)(dp + rb);
            float2 B1 = *(const float2*)(dp + rb + 2);
            float w0 = fmaf(rs, B0.x, A0.x);
            float w1 = fmaf(rs, B0.y, A0.y);
            float w2 = fmaf(rs, B1.x, A1.x);
            float w3 = fmaf(rs, B1.y, A1.y);
            v_s[0 * 2048 + idx] = w0 - w2;
            v_s[1 * 2048 + idx] = w1 + w2;
            v_s[2 * 2048 + idx] = w2 - w1;
            v_s[3 * 2048 + idx] = w1 - w3;
        }
        __syncthreads();

        float a0i = c_A0[ig], a1i = c_A1[ig];

        #pragma unroll
        for (int jj = 0; jj < 4; ++jj) {
            const ulonglong2* up =
                (const ulonglong2*)(ubase + (size_t)(ig * 4 + jj) * 4096) + cog;
            const float* vp = v_s + jj * 2048 + tp;

            ull m00 = 0, m01 = 0, m10 = 0, m11 = 0;
            #pragma unroll 4
            for (int ci = 0; ci < 64; ++ci) {
                ulonglong2 u = __ldg(up + ci * 16);
                float2 vv = *(const float2*)(vp + ci * 32);
                ull v0d, v1d;
                DUP2(v0d, vv.x);
                DUP2(v1d, vv.y);
                FMA2(m00, u.x, v0d);
                FMA2(m01, u.x, v1d);
                FMA2(m10, u.y, v0d);
                FMA2(m11, u.y, v1d);
            }

            // fold M into O accumulators with A^T coefficients
            const float CJ0[4] = {1.f, 1.f, 1.f, 0.f};
            const float CJ1[4] = {0.f, 1.f, -1.f, -1.f};
            #pragma unroll
            for (int r = 0; r < 2; ++r) {
                float rc = r ? a1i : a0i;
                #pragma unroll
                for (int c = 0; c < 2; ++c) {
                    float cc = c ? CJ1[jj] : CJ0[jj];
                    if (cc == 0.f) continue;     // compile-time prune
                    float coef = rc * cc;
                    ull cd; DUP2(cd, coef);
                    FMA2(oacc[0][0][r][c], m00, cd);
                    FMA2(oacc[0][1][r][c], m01, cd);
                    FMA2(oacc[1][0][r][c], m10, cd);
                    FMA2(oacc[1][1][r][c], m11, cd);
                }
            }
        }
    }

    // ---- writeback: unpack co pairs, store float2 per output row ----
    float* outp = g_co + (size_t)(sub * 8 + b) * 64 * 4096;
    int co4 = cog * 4;
    #pragma unroll
    for (int l = 0; l < 2; ++l) {
        int tl = tp + l;
        int oy = th0 + (tl >> 3) * 2;
        int ox = tw0 + (tl & 7) * 2;
        #pragma unroll
        for (int p = 0; p < 2; ++p) {
            #pragma unroll
            for (int r = 0; r < 2; ++r) {
                float lo0, hi0, lo1, hi1;
                asm("mov.b64 {%0, %1}, %2;" : "=f"(lo0), "=f"(hi0)
                    : "l"(oacc[p][l][r][0]));
                asm("mov.b64 {%0, %1}, %2;" : "=f"(lo1), "=f"(hi1)
                    : "l"(oacc[p][l][r][1]));
                size_t off = (size_t)(oy + r) * 64 + ox;
                *(float2*)(outp + (size_t)(co4 + 2 * p)     * 4096 + off) =
                    make_float2(lo0, lo1);
                *(float2*)(outp + (size_t)(co4 + 2 * p + 1) * 4096 + off) =
                    make_float2(hi0, hi1);
            }
        }
    }
}

// ---------------------------------------------------------------------------
// Kernel 4: inverse Haar DWT -> final output
// ---------------------------------------------------------------------------
__global__ void idwt_kernel(float* __restrict__ out) {
    int idx = blockIdx.x * blockDim.x + threadIdx.x;
    if (idx >= SB_STRIDE) return;
    int w  = idx & 63;
    int h  = (idx >> 6) & 63;
    int bc = idx >> 12;

    float ll = g_co[idx];
    float h0 = g_co[SB_STRIDE + idx];
    float h1 = g_co[2 * SB_STRIDE + idx];
    float hh = g_co[3 * SB_STRIDE + idx];

    float a  = (ll + h0 + h1 + hh) * 0.5f;
    float b_ = (ll + h0 - h1 - hh) * 0.5f;
    float c_ = (ll - h0 + h1 - hh) * 0.5f;
    float d_ = (ll - h0 - h1 + hh) * 0.5f;

    float2* top = (float2*)(out + ((size_t)bc * 128 + 2 * h) * 128);
    float2* bot = (float2*)(out + ((size_t)bc * 128 + 2 * h + 1) * 128);
    top[w] = make_float2(a, b_);
    bot[w] = make_float2(c_, d_);
}

// ---------------------------------------------------------------------------
// Launch
// ---------------------------------------------------------------------------
extern "C" void kernel_launch(void* const* d_in, const int* in_sizes, int n_in,
                              void* d_out, int out_size) {
    const float* x  = (const float*)d_in[0];
    const float* wt = (const float*)d_in[1];
    const float* aw = (const float*)d_in[2];
    const float* ab = (const float*)d_in[3];
    float* out = (float*)d_out;

    static const int kConvSmem = (11520 + 4 * 2048) * 4;   // 78848 B
    cudaFuncSetAttribute(wino_conv,
                         cudaFuncAttributeMaxDynamicSharedMemorySize, kConvSmem);

    dwt_kernel<<<NBC, 256>>>(x);
    attn_kernel<<<1, 32>>>(aw, ab);
    wino_mix<<<dim3(16, 4, 8), 256>>>(wt);
    wino_conv<<<dim3(32, 4, 8), 256, kConvSmem>>>();
    idwt_kernel<<<8192, 256>>>(out);
}

// round 7
// speedup vs baseline: 1.3005x; 1.3005x over previous
#include <cuda_runtime.h>
#include <math.h>

typedef unsigned long long ull;

// ---------------------------------------------------------------------------
// Scratch (static device globals; no runtime allocation)
// ---------------------------------------------------------------------------
__device__ float g_sb[4 * 8 * 64 * 64 * 64];        // subbands [sub][b][c][64][64]
__device__ float g_co[4 * 8 * 64 * 64 * 64];        // conv outs [sub][b][co][64][64]
__device__ float g_sums[8 * 64 * 4];                // per (b,c,sub) sums
__device__ float g_att[8 * 4 * 4];                  // attention [b][sub][k]
__device__ float g_mku[8 * 4 * 16 * 64 * 64];       // Winograd U [b][sub][t][ci][co]

#define SB_STRIDE  2097152
#define NBC        512

// Winograd constant tables (B^T row/col combination selectors, A^T coeffs)
__constant__ int   c_ra[4] = {0, 1, 2, 1};
__constant__ int   c_rb[4] = {2, 2, 1, 3};
__constant__ float c_rs[4] = {-1.f, 1.f, -1.f, -1.f};
__constant__ float c_A0[4] = {1.f, 1.f, 1.f, 0.f};   // A^T row 0
__constant__ float c_A1[4] = {0.f, 1.f, -1.f, -1.f}; // A^T row 1

#define FMA2(acc, a, b) asm volatile("fma.rn.f32x2 %0, %1, %2, %0;" \
                                     : "+l"(acc) : "l"(a), "l"(b))
#define DUP2(dst, v)    asm("mov.b64 %0, {%1, %1};" : "=l"(dst) : "f"(v))

// ---------------------------------------------------------------------------
// Kernel 1: Haar DWT fused with per-(b,c) subband sums
// ---------------------------------------------------------------------------
__global__ void dwt_kernel(const float* __restrict__ x) {
    int bc  = blockIdx.x;
    int tid = threadIdx.x;
    int ow  = tid & 63;
    int oh0 = tid >> 6;
    const float* xp = x + (size_t)bc * 128 * 128;

    float s0 = 0.f, s1 = 0.f, s2 = 0.f, s3 = 0.f;
    #pragma unroll 4
    for (int it = 0; it < 16; ++it) {
        int oh = oh0 + it * 4;
        float2 t  = ((const float2*)(xp + (2 * oh)     * 128))[ow];
        float2 bo = ((const float2*)(xp + (2 * oh + 1) * 128))[ow];
        float a = t.x, b_ = t.y, c_ = bo.x, d_ = bo.y;
        float ll = (a + b_ + c_ + d_) * 0.5f;
        float h0 = (a + b_ - c_ - d_) * 0.5f;
        float h1 = (a - b_ + c_ - d_) * 0.5f;
        float hh = (a - b_ - c_ + d_) * 0.5f;
        int o = bc * 4096 + oh * 64 + ow;
        g_sb[0 * SB_STRIDE + o] = ll;
        g_sb[1 * SB_STRIDE + o] = h0;
        g_sb[2 * SB_STRIDE + o] = h1;
        g_sb[3 * SB_STRIDE + o] = hh;
        s0 += ll; s1 += h0; s2 += h1; s3 += hh;
    }

    #pragma unroll
    for (int off = 16; off; off >>= 1) {
        s0 += __shfl_down_sync(0xffffffffu, s0, off);
        s1 += __shfl_down_sync(0xffffffffu, s1, off);
        s2 += __shfl_down_sync(0xffffffffu, s2, off);
        s3 += __shfl_down_sync(0xffffffffu, s3, off);
    }
    __shared__ float red[8][4];
    int warp = tid >> 5, lane = tid & 31;
    if (lane == 0) {
        red[warp][0] = s0; red[warp][1] = s1;
        red[warp][2] = s2; red[warp][3] = s3;
    }
    __syncthreads();
    if (tid < 4) {
        float s = 0.f;
        #pragma unroll
        for (int w = 0; w < 8; ++w) s += red[w][tid];
        g_sums[bc * 4 + tid] = s;
    }
}

// ---------------------------------------------------------------------------
// Kernel 2a: attention logits + softmax
// ---------------------------------------------------------------------------
__global__ void attn_kernel(const float* __restrict__ attn_w,
                            const float* __restrict__ attn_b) {
    int t = threadIdx.x;
    if (t >= 32) return;
    int b = t >> 2, i = t & 3;
    float logits[4];
    #pragma unroll
    for (int k = 0; k < 4; ++k) {
        float acc = 0.f;
        for (int c = 0; c < 64; ++c)
            acc += attn_w[k * 64 + c] * g_sums[(b * 64 + c) * 4 + i];
        logits[k] = acc * (1.0f / 4096.0f) + attn_b[k];
    }
    float m = fmaxf(fmaxf(logits[0], logits[1]), fmaxf(logits[2], logits[3]));
    float e[4]; float s = 0.f;
    #pragma unroll
    for (int k = 0; k < 4; ++k) { e[k] = expf(logits[k] - m); s += e[k]; }
    float inv = 1.0f / s;
    #pragma unroll
    for (int k = 0; k < 4; ++k) g_att[(b * 4 + i) * 4 + k] = e[k] * inv;
}

// ---------------------------------------------------------------------------
// Kernel 2b: mix kernels with attention AND transform to Winograd U.
//   U[b][i][t=(r*4+cl)][ci][co] = (G g Gt)[r][cl],  g = sum_k att * wt[k][i]
// ---------------------------------------------------------------------------
__global__ void wino_mix(const float* __restrict__ wt) {
    int cig = blockIdx.x, i = blockIdx.y, b = blockIdx.z;
    int bi = b * 4 + i;
    __shared__ float s[36 * 65];

    int tid = threadIdx.x;
    int co  = tid & 63;
    int cil = tid >> 6;

    float g9[9];
    #pragma unroll
    for (int q = 0; q < 9; ++q) g9[q] = 0.f;

    #pragma unroll
    for (int k = 0; k < 4; ++k) {
        float ak = g_att[bi * 4 + k];
        const float* src = wt + ((size_t)(k * 4 + i) * 64) * 576 + cig * 36;
        __syncthreads();
        for (int idx = tid; idx < 64 * 36; idx += 256) {
            int c = idx / 36;
            int j = idx - c * 36;
            s[j * 65 + c] = src[(size_t)c * 576 + j];
        }
        __syncthreads();
        #pragma unroll
        for (int q = 0; q < 9; ++q)
            g9[q] += ak * s[(cil * 9 + q) * 65 + co];
    }

    // U = G g G^T ; G = [[1,0,0],[.5,.5,.5],[.5,-.5,.5],[0,0,1]]
    float T[4][3];
    #pragma unroll
    for (int c = 0; c < 3; ++c) {
        float a = g9[c], bb = g9[3 + c], cc = g9[6 + c];
        T[0][c] = a;
        T[1][c] = 0.5f * (a + bb + cc);
        T[2][c] = 0.5f * (a - bb + cc);
        T[3][c] = cc;
    }
    float* dst = g_mku + ((size_t)bi * 16) * 4096 + (cig * 4 + cil) * 64 + co;
    #pragma unroll
    for (int r = 0; r < 4; ++r) {
        float u0 = T[r][0], u1b = T[r][1], u2 = T[r][2];
        float U0 = u0;
        float U1 = 0.5f * (u0 + u1b + u2);
        float U2 = 0.5f * (u0 - u1b + u2);
        float U3 = u2;
        dst[(r * 4 + 0) * 4096] = U0;
        dst[(r * 4 + 1) * 4096] = U1;
        dst[(r * 4 + 2) * 4096] = U2;
        dst[(r * 4 + 3) * 4096] = U3;
    }
}

// ---------------------------------------------------------------------------
// Kernel 3: fused Winograd F(2x2,3x3) dynamic conv.  U STAGED IN SMEM.
// Block = 256 threads, 64 cout x 32 tiles (8x16 output px) of one (b,sub).
// smem: raw halo 64ci x 10 x 18  |  4 V buffers (64ci x 32t)  |  U tile 16KB
// Thread: cog = tid&15 (co pack of 4), tp = tile pair. GEMM reads smem only.
// ---------------------------------------------------------------------------
__global__ void __launch_bounds__(256, 2) wino_conv() {
    extern __shared__ float sm[];
    float* raw_s = sm;                    // 11520 floats
    float* v_s   = sm + 11520;            // 4 * 2048 floats
    float* u_s   = sm + 11520 + 8192;     // 4096 floats (16 KB)

    int b   = blockIdx.z;
    int sub = blockIdx.y;
    int tb  = blockIdx.x;               // 0..31
    int th0 = (tb >> 2) * 8;            // output row origin
    int tw0 = (tb & 3) * 16;            // output col origin
    int bi  = b * 4 + sub;

    int tid = threadIdx.x;
    int cog = tid & 15;                 // co4 = cog*4
    int tp  = (tid >> 4) * 2;           // tile pair base (0..30)

    const float* sbp = g_sb + (size_t)(sub * 8 + b) * 64 * 4096;

    // ---- stage raw halo: 64 ci x 10 x 18 (zero padded) ----
    for (int idx = tid; idx < 11520; idx += 256) {
        int ci  = idx / 180;
        int rem = idx - ci * 180;
        int y   = rem / 18;
        int xx  = rem - y * 18;
        int ih  = th0 - 1 + y;
        int iw  = tw0 - 1 + xx;
        float v = 0.f;
        if ((unsigned)ih < 64u && (unsigned)iw < 64u)
            v = sbp[ci * 4096 + ih * 64 + iw];
        raw_s[idx] = v;
    }

    ull oacc[2][2][2][2];   // [co-pair p][tile l][out row r][out col c]
    #pragma unroll
    for (int p = 0; p < 2; ++p)
        #pragma unroll
        for (int l = 0; l < 2; ++l)
            #pragma unroll
            for (int r = 0; r < 2; ++r)
                #pragma unroll
                for (int c = 0; c < 2; ++c) oacc[p][l][r][c] = 0ull;

    const float* ubase = g_mku + (size_t)bi * 16 * 4096;

    for (int ig = 0; ig < 4; ++ig) {    // B^T row-combination group
        int   ra = c_ra[ig] * 18;
        int   rb = c_rb[ig] * 18;
        float rs = c_rs[ig];

        __syncthreads();                // prev GEMMs done reading v_s
        // ---- transform: V[ig][j=0..3] for all (ci, tile) ----
        #pragma unroll
        for (int q = 0; q < 8; ++q) {
            int idx = tid + q * 256;    // 2048 cells
            int ci  = idx >> 5;
            int tl  = idx & 31;
            const float* dp = &raw_s[ci * 180 + (tl >> 3) * 36 + (tl & 7) * 2];
            float2 A0 = *(const float2*)(dp + ra);
            float2 A1 = *(const float2*)(dp + ra + 2);
            float2 B0 = *(const float2*)(dp + rb);
            float2 B1 = *(const float2*)(dp + rb + 2);
            float w0 = fmaf(rs, B0.x, A0.x);
            float w1 = fmaf(rs, B0.y, A0.y);
            float w2 = fmaf(rs, B1.x, A1.x);
            float w3 = fmaf(rs, B1.y, A1.y);
            v_s[0 * 2048 + idx] = w0 - w2;
            v_s[1 * 2048 + idx] = w1 + w2;
            v_s[2 * 2048 + idx] = w2 - w1;
            v_s[3 * 2048 + idx] = w1 - w3;
        }

        float a0i = c_A0[ig], a1i = c_A1[ig];

        #pragma unroll 1
        for (int jj = 0; jj < 4; ++jj) {
            // ---- stage U(ig,jj) tile: 4096 floats, coalesced float4 ----
            __syncthreads();            // prev GEMM done reading u_s
                                        // (jj==0: also fences v_s writes)
            {
                const float4* usrc =
                    (const float4*)(ubase + (size_t)(ig * 4 + jj) * 4096);
                float4* udst = (float4*)u_s;
                #pragma unroll
                for (int q = 0; q < 4; ++q)
                    udst[tid + q * 256] = usrc[tid + q * 256];
            }
            __syncthreads();            // u_s (and v_s) visible

            const ulonglong2* us = (const ulonglong2*)u_s + cog;
            const float* vp = v_s + jj * 2048 + tp;

            ull m00 = 0, m01 = 0, m10 = 0, m11 = 0;
            #pragma unroll 8
            for (int ci = 0; ci < 64; ++ci) {
                ulonglong2 u = us[ci * 16];
                float2 vv = *(const float2*)(vp + ci * 32);
                ull v0d, v1d;
                DUP2(v0d, vv.x);
                DUP2(v1d, vv.y);
                FMA2(m00, u.x, v0d);
                FMA2(m01, u.x, v1d);
                FMA2(m10, u.y, v0d);
                FMA2(m11, u.y, v1d);
            }

            // fold M into O accumulators with A^T coefficients
            const float CJ0[4] = {1.f, 1.f, 1.f, 0.f};
            const float CJ1[4] = {0.f, 1.f, -1.f, -1.f};
            #pragma unroll
            for (int r = 0; r < 2; ++r) {
                float rc = r ? a1i : a0i;
                #pragma unroll
                for (int c = 0; c < 2; ++c) {
                    float cc = c ? CJ1[jj] : CJ0[jj];
                    if (cc == 0.f) continue;     // compile-time prune
                    float coef = rc * cc;
                    ull cd; DUP2(cd, coef);
                    FMA2(oacc[0][0][r][c], m00, cd);
                    FMA2(oacc[0][1][r][c], m01, cd);
                    FMA2(oacc[1][0][r][c], m10, cd);
                    FMA2(oacc[1][1][r][c], m11, cd);
                }
            }
        }
    }

    // ---- writeback: unpack co pairs, store float2 per output row ----
    float* outp = g_co + (size_t)(sub * 8 + b) * 64 * 4096;
    int co4 = cog * 4;
    #pragma unroll
    for (int l = 0; l < 2; ++l) {
        int tl = tp + l;
        int oy = th0 + (tl >> 3) * 2;
        int ox = tw0 + (tl & 7) * 2;
        #pragma unroll
        for (int p = 0; p < 2; ++p) {
            #pragma unroll
            for (int r = 0; r < 2; ++r) {
                float lo0, hi0, lo1, hi1;
                asm("mov.b64 {%0, %1}, %2;" : "=f"(lo0), "=f"(hi0)
                    : "l"(oacc[p][l][r][0]));
                asm("mov.b64 {%0, %1}, %2;" : "=f"(lo1), "=f"(hi1)
                    : "l"(oacc[p][l][r][1]));
                size_t off = (size_t)(oy + r) * 64 + ox;
                *(float2*)(outp + (size_t)(co4 + 2 * p)     * 4096 + off) =
                    make_float2(lo0, lo1);
                *(float2*)(outp + (size_t)(co4 + 2 * p + 1) * 4096 + off) =
                    make_float2(hi0, hi1);
            }
        }
    }
}

// ---------------------------------------------------------------------------
// Kernel 4: inverse Haar DWT -> final output
// ---------------------------------------------------------------------------
__global__ void idwt_kernel(float* __restrict__ out) {
    int idx = blockIdx.x * blockDim.x + threadIdx.x;
    if (idx >= SB_STRIDE) return;
    int w  = idx & 63;
    int h  = (idx >> 6) & 63;
    int bc = idx >> 12;

    float ll = g_co[idx];
    float h0 = g_co[SB_STRIDE + idx];
    float h1 = g_co[2 * SB_STRIDE + idx];
    float hh = g_co[3 * SB_STRIDE + idx];

    float a  = (ll + h0 + h1 + hh) * 0.5f;
    float b_ = (ll + h0 - h1 - hh) * 0.5f;
    float c_ = (ll - h0 + h1 - hh) * 0.5f;
    float d_ = (ll - h0 - h1 + hh) * 0.5f;

    float2* top = (float2*)(out + ((size_t)bc * 128 + 2 * h) * 128);
    float2* bot = (float2*)(out + ((size_t)bc * 128 + 2 * h + 1) * 128);
    top[w] = make_float2(a, b_);
    bot[w] = make_float2(c_, d_);
}

// ---------------------------------------------------------------------------
// Launch
// ---------------------------------------------------------------------------
extern "C" void kernel_launch(void* const* d_in, const int* in_sizes, int n_in,
                              void* d_out, int out_size) {
    const float* x  = (const float*)d_in[0];
    const float* wt = (const float*)d_in[1];
    const float* aw = (const float*)d_in[2];
    const float* ab = (const float*)d_in[3];
    float* out = (float*)d_out;

    static const int kConvSmem = (11520 + 4 * 2048 + 4096) * 4;   // 95232 B
    cudaFuncSetAttribute(wino_conv,
                         cudaFuncAttributeMaxDynamicSharedMemorySize, kConvSmem);

    dwt_kernel<<<NBC, 256>>>(x);
    attn_kernel<<<1, 32>>>(aw, ab);
    wino_mix<<<dim3(16, 4, 8), 256>>>(wt);
    wino_conv<<<dim3(32, 4, 8), 256, kConvSmem>>>();
    idwt_kernel<<<8192, 256>>>(out);
}

// round 8
// speedup vs baseline: 1.4859x; 1.1426x over previous
#include <cuda_runtime.h>
#include <math.h>

typedef unsigned long long ull;

// ---------------------------------------------------------------------------
// Scratch (static device globals; no runtime allocation)
// ---------------------------------------------------------------------------
__device__ float g_sb[4 * 8 * 64 * 64 * 64];        // subbands [sub][b][c][64][64]
__device__ float g_co[4 * 8 * 64 * 64 * 64];        // conv outs [sub][b][co][64][64]
__device__ float g_sums[8 * 64 * 4];                // per (b,c,sub) sums
__device__ float g_att[8 * 4 * 4];                  // attention [b][sub][k]
__device__ float g_mku[8 * 4 * 16 * 64 * 64];       // Winograd U [b][sub][t][ci][co]

#define SB_STRIDE  2097152
#define NBC        512

// Winograd constant tables (B^T row/col combination selectors, A^T coeffs)
__constant__ int   c_ra[4] = {0, 1, 2, 1};
__constant__ int   c_rb[4] = {2, 2, 1, 3};
__constant__ float c_rs[4] = {-1.f, 1.f, -1.f, -1.f};
__constant__ float c_A0[4] = {1.f, 1.f, 1.f, 0.f};   // A^T row 0
__constant__ float c_A1[4] = {0.f, 1.f, -1.f, -1.f}; // A^T row 1

#define FMA2(acc, a, b) asm volatile("fma.rn.f32x2 %0, %1, %2, %0;" \
                                     : "+l"(acc) : "l"(a), "l"(b))
#define DUP2(dst, v)    asm("mov.b64 %0, {%1, %1};" : "=l"(dst) : "f"(v))

// ---------------------------------------------------------------------------
// Kernel 1: Haar DWT fused with per-(b,c) subband sums
// ---------------------------------------------------------------------------
__global__ void dwt_kernel(const float* __restrict__ x) {
    int bc  = blockIdx.x;
    int tid = threadIdx.x;
    int ow  = tid & 63;
    int oh0 = tid >> 6;
    const float* xp = x + (size_t)bc * 128 * 128;

    float s0 = 0.f, s1 = 0.f, s2 = 0.f, s3 = 0.f;
    #pragma unroll 4
    for (int it = 0; it < 16; ++it) {
        int oh = oh0 + it * 4;
        float2 t  = ((const float2*)(xp + (2 * oh)     * 128))[ow];
        float2 bo = ((const float2*)(xp + (2 * oh + 1) * 128))[ow];
        float a = t.x, b_ = t.y, c_ = bo.x, d_ = bo.y;
        float ll = (a + b_ + c_ + d_) * 0.5f;
        float h0 = (a + b_ - c_ - d_) * 0.5f;
        float h1 = (a - b_ + c_ - d_) * 0.5f;
        float hh = (a - b_ - c_ + d_) * 0.5f;
        int o = bc * 4096 + oh * 64 + ow;
        g_sb[0 * SB_STRIDE + o] = ll;
        g_sb[1 * SB_STRIDE + o] = h0;
        g_sb[2 * SB_STRIDE + o] = h1;
        g_sb[3 * SB_STRIDE + o] = hh;
        s0 += ll; s1 += h0; s2 += h1; s3 += hh;
    }

    #pragma unroll
    for (int off = 16; off; off >>= 1) {
        s0 += __shfl_down_sync(0xffffffffu, s0, off);
        s1 += __shfl_down_sync(0xffffffffu, s1, off);
        s2 += __shfl_down_sync(0xffffffffu, s2, off);
        s3 += __shfl_down_sync(0xffffffffu, s3, off);
    }
    __shared__ float red[8][4];
    int warp = tid >> 5, lane = tid & 31;
    if (lane == 0) {
        red[warp][0] = s0; red[warp][1] = s1;
        red[warp][2] = s2; red[warp][3] = s3;
    }
    __syncthreads();
    if (tid < 4) {
        float s = 0.f;
        #pragma unroll
        for (int w = 0; w < 8; ++w) s += red[w][tid];
        g_sums[bc * 4 + tid] = s;
    }
}

// ---------------------------------------------------------------------------
// Kernel 2a: attention logits + softmax
// ---------------------------------------------------------------------------
__global__ void attn_kernel(const float* __restrict__ attn_w,
                            const float* __restrict__ attn_b) {
    int t = threadIdx.x;
    if (t >= 32) return;
    int b = t >> 2, i = t & 3;
    float logits[4];
    #pragma unroll
    for (int k = 0; k < 4; ++k) {
        float acc = 0.f;
        for (int c = 0; c < 64; ++c)
            acc += attn_w[k * 64 + c] * g_sums[(b * 64 + c) * 4 + i];
        logits[k] = acc * (1.0f / 4096.0f) + attn_b[k];
    }
    float m = fmaxf(fmaxf(logits[0], logits[1]), fmaxf(logits[2], logits[3]));
    float e[4]; float s = 0.f;
    #pragma unroll
    for (int k = 0; k < 4; ++k) { e[k] = expf(logits[k] - m); s += e[k]; }
    float inv = 1.0f / s;
    #pragma unroll
    for (int k = 0; k < 4; ++k) g_att[(b * 4 + i) * 4 + k] = e[k] * inv;
}

// ---------------------------------------------------------------------------
// Kernel 2b: mix kernels with attention AND transform to Winograd U.
//   U[b][i][t=(r*4+cl)][ci][co] = (G g Gt)[r][cl],  g = sum_k att * wt[k][i]
// ---------------------------------------------------------------------------
__global__ void wino_mix(const float* __restrict__ wt) {
    int cig = blockIdx.x, i = blockIdx.y, b = blockIdx.z;
    int bi = b * 4 + i;
    __shared__ float s[36 * 65];

    int tid = threadIdx.x;
    int co  = tid & 63;
    int cil = tid >> 6;

    float g9[9];
    #pragma unroll
    for (int q = 0; q < 9; ++q) g9[q] = 0.f;

    #pragma unroll
    for (int k = 0; k < 4; ++k) {
        float ak = g_att[bi * 4 + k];
        const float* src = wt + ((size_t)(k * 4 + i) * 64) * 576 + cig * 36;
        __syncthreads();
        for (int idx = tid; idx < 64 * 36; idx += 256) {
            int c = idx / 36;
            int j = idx - c * 36;
            s[j * 65 + c] = src[(size_t)c * 576 + j];
        }
        __syncthreads();
        #pragma unroll
        for (int q = 0; q < 9; ++q)
            g9[q] += ak * s[(cil * 9 + q) * 65 + co];
    }

    // U = G g G^T ; G = [[1,0,0],[.5,.5,.5],[.5,-.5,.5],[0,0,1]]
    float T[4][3];
    #pragma unroll
    for (int c = 0; c < 3; ++c) {
        float a = g9[c], bb = g9[3 + c], cc = g9[6 + c];
        T[0][c] = a;
        T[1][c] = 0.5f * (a + bb + cc);
        T[2][c] = 0.5f * (a - bb + cc);
        T[3][c] = cc;
    }
    float* dst = g_mku + ((size_t)bi * 16) * 4096 + (cig * 4 + cil) * 64 + co;
    #pragma unroll
    for (int r = 0; r < 4; ++r) {
        float u0 = T[r][0], u1b = T[r][1], u2 = T[r][2];
        float U0 = u0;
        float U1 = 0.5f * (u0 + u1b + u2);
        float U2 = 0.5f * (u0 - u1b + u2);
        float U3 = u2;
        dst[(r * 4 + 0) * 4096] = U0;
        dst[(r * 4 + 1) * 4096] = U1;
        dst[(r * 4 + 2) * 4096] = U2;
        dst[(r * 4 + 3) * 4096] = U3;
    }
}

// ---------------------------------------------------------------------------
// Kernel 3: fused Winograd F(2x2,3x3) dynamic conv.  U staged in smem.
// Block = 256 threads, 64 cout x 32 tiles (8x16 output px) of one (b,sub).
// WAVEFRONT-BALANCED warp map: each warp covers 4 co-groups x 8 tile-groups
//   cog = bits[6:5,4:3] of tid ; tpg = bits[7,2:0]  (bijective remap)
// -> U LDS.128 = 64B/warp = 1 wavefront ; V LDS.64 = 64B/warp = 1 wavefront.
// ---------------------------------------------------------------------------
__global__ void __launch_bounds__(256, 2) wino_conv() {
    extern __shared__ float sm[];
    float* raw_s = sm;                    // 11520 floats
    float* v_s   = sm + 11520;            // 4 * 2048 floats
    float* u_s   = sm + 11520 + 8192;     // 4096 floats (16 KB)

    int b   = blockIdx.z;
    int sub = blockIdx.y;
    int tb  = blockIdx.x;               // 0..31
    int th0 = (tb >> 2) * 8;            // output row origin
    int tw0 = (tb & 3) * 16;            // output col origin
    int bi  = b * 4 + sub;

    int tid = threadIdx.x;
    // warp-balanced mapping: warp spans 4 cogs (64B U) and 8 tpgs (64B V)
    int cog = (((tid >> 5) & 3) << 2) | ((tid >> 3) & 3);   // 0..15
    int tp  = ((((tid >> 7) << 3) | (tid & 7)) << 1);       // 0,2,..,30

    const float* sbp = g_sb + (size_t)(sub * 8 + b) * 64 * 4096;

    // ---- stage raw halo: 64 ci x 10 x 18 (zero padded) ----
    for (int idx = tid; idx < 11520; idx += 256) {
        int ci  = idx / 180;
        int rem = idx - ci * 180;
        int y   = rem / 18;
        int xx  = rem - y * 18;
        int ih  = th0 - 1 + y;
        int iw  = tw0 - 1 + xx;
        float v = 0.f;
        if ((unsigned)ih < 64u && (unsigned)iw < 64u)
            v = sbp[ci * 4096 + ih * 64 + iw];
        raw_s[idx] = v;
    }

    ull oacc[2][2][2][2];   // [co-pair p][tile l][out row r][out col c]
    #pragma unroll
    for (int p = 0; p < 2; ++p)
        #pragma unroll
        for (int l = 0; l < 2; ++l)
            #pragma unroll
            for (int r = 0; r < 2; ++r)
                #pragma unroll
                for (int c = 0; c < 2; ++c) oacc[p][l][r][c] = 0ull;

    const float* ubase = g_mku + (size_t)bi * 16 * 4096;

    for (int ig = 0; ig < 4; ++ig) {    // B^T row-combination group
        int   ra = c_ra[ig] * 18;
        int   rb = c_rb[ig] * 18;
        float rs = c_rs[ig];

        __syncthreads();                // prev GEMMs done reading v_s
        // ---- transform: V[ig][j=0..3] for all (ci, tile) ----
        #pragma unroll
        for (int q = 0; q < 8; ++q) {
            int idx = tid + q * 256;    // 2048 cells
            int ci  = idx >> 5;
            int tl  = idx & 31;
            const float* dp = &raw_s[ci * 180 + (tl >> 3) * 36 + (tl & 7) * 2];
            float2 A0 = *(const float2*)(dp + ra);
            float2 A1 = *(const float2*)(dp + ra + 2);
            float2 B0 = *(const float2*)(dp + rb);
            float2 B1 = *(const float2*)(dp + rb + 2);
            float w0 = fmaf(rs, B0.x, A0.x);
            float w1 = fmaf(rs, B0.y, A0.y);
            float w2 = fmaf(rs, B1.x, A1.x);
            float w3 = fmaf(rs, B1.y, A1.y);
            v_s[0 * 2048 + idx] = w0 - w2;
            v_s[1 * 2048 + idx] = w1 + w2;
            v_s[2 * 2048 + idx] = w2 - w1;
            v_s[3 * 2048 + idx] = w1 - w3;
        }

        float a0i = c_A0[ig], a1i = c_A1[ig];

        #pragma unroll 1
        for (int jj = 0; jj < 4; ++jj) {
            // ---- stage U(ig,jj) tile: 4096 floats, coalesced float4 ----
            __syncthreads();            // prev GEMM done reading u_s
                                        // (jj==0: also fences v_s writes)
            {
                const float4* usrc =
                    (const float4*)(ubase + (size_t)(ig * 4 + jj) * 4096);
                float4* udst = (float4*)u_s;
                #pragma unroll
                for (int q = 0; q < 4; ++q)
                    udst[tid + q * 256] = usrc[tid + q * 256];
            }
            __syncthreads();            // u_s (and v_s) visible

            const ulonglong2* us = (const ulonglong2*)u_s + cog;
            const float* vp = v_s + jj * 2048 + tp;

            ull m00 = 0, m01 = 0, m10 = 0, m11 = 0;
            #pragma unroll 8
            for (int ci = 0; ci < 64; ++ci) {
                ulonglong2 u = us[ci * 16];
                float2 vv = *(const float2*)(vp + ci * 32);
                ull v0d, v1d;
                DUP2(v0d, vv.x);
                DUP2(v1d, vv.y);
                FMA2(m00, u.x, v0d);
                FMA2(m01, u.x, v1d);
                FMA2(m10, u.y, v0d);
                FMA2(m11, u.y, v1d);
            }

            // fold M into O accumulators with A^T coefficients
            const float CJ0[4] = {1.f, 1.f, 1.f, 0.f};
            const float CJ1[4] = {0.f, 1.f, -1.f, -1.f};
            #pragma unroll
            for (int r = 0; r < 2; ++r) {
                float rc = r ? a1i : a0i;
                #pragma unroll
                for (int c = 0; c < 2; ++c) {
                    float cc = c ? CJ1[jj] : CJ0[jj];
                    if (cc == 0.f) continue;     // compile-time prune
                    float coef = rc * cc;
                    ull cd; DUP2(cd, coef);
                    FMA2(oacc[0][0][r][c], m00, cd);
                    FMA2(oacc[0][1][r][c], m01, cd);
                    FMA2(oacc[1][0][r][c], m10, cd);
                    FMA2(oacc[1][1][r][c], m11, cd);
                }
            }
        }
    }

    // ---- writeback: unpack co pairs, store float2 per output row ----
    float* outp = g_co + (size_t)(sub * 8 + b) * 64 * 4096;
    int co4 = cog * 4;
    #pragma unroll
    for (int l = 0; l < 2; ++l) {
        int tl = tp + l;
        int oy = th0 + (tl >> 3) * 2;
        int ox = tw0 + (tl & 7) * 2;
        #pragma unroll
        for (int p = 0; p < 2; ++p) {
            #pragma unroll
            for (int r = 0; r < 2; ++r) {
                float lo0, hi0, lo1, hi1;
                asm("mov.b64 {%0, %1}, %2;" : "=f"(lo0), "=f"(hi0)
                    : "l"(oacc[p][l][r][0]));
                asm("mov.b64 {%0, %1}, %2;" : "=f"(lo1), "=f"(hi1)
                    : "l"(oacc[p][l][r][1]));
                size_t off = (size_t)(oy + r) * 64 + ox;
                *(float2*)(outp + (size_t)(co4 + 2 * p)     * 4096 + off) =
                    make_float2(lo0, lo1);
                *(float2*)(outp + (size_t)(co4 + 2 * p + 1) * 4096 + off) =
                    make_float2(hi0, hi1);
            }
        }
    }
}

// ---------------------------------------------------------------------------
// Kernel 4: inverse Haar DWT -> final output
// ---------------------------------------------------------------------------
__global__ void idwt_kernel(float* __restrict__ out) {
    int idx = blockIdx.x * blockDim.x + threadIdx.x;
    if (idx >= SB_STRIDE) return;
    int w  = idx & 63;
    int h  = (idx >> 6) & 63;
    int bc = idx >> 12;

    float ll = g_co[idx];
    float h0 = g_co[SB_STRIDE + idx];
    float h1 = g_co[2 * SB_STRIDE + idx];
    float hh = g_co[3 * SB_STRIDE + idx];

    float a  = (ll + h0 + h1 + hh) * 0.5f;
    float b_ = (ll + h0 - h1 - hh) * 0.5f;
    float c_ = (ll - h0 + h1 - hh) * 0.5f;
    float d_ = (ll - h0 - h1 + hh) * 0.5f;

    float2* top = (float2*)(out + ((size_t)bc * 128 + 2 * h) * 128);
    float2* bot = (float2*)(out + ((size_t)bc * 128 + 2 * h + 1) * 128);
    top[w] = make_float2(a, b_);
    bot[w] = make_float2(c_, d_);
}

// ---------------------------------------------------------------------------
// Launch
// ---------------------------------------------------------------------------
extern "C" void kernel_launch(void* const* d_in, const int* in_sizes, int n_in,
                              void* d_out, int out_size) {
    const float* x  = (const float*)d_in[0];
    const float* wt = (const float*)d_in[1];
    const float* aw = (const float*)d_in[2];
    const float* ab = (const float*)d_in[3];
    float* out = (float*)d_out;

    static const int kConvSmem = (11520 + 4 * 2048 + 4096) * 4;   // 95232 B
    cudaFuncSetAttribute(wino_conv,
                         cudaFuncAttributeMaxDynamicSharedMemorySize, kConvSmem);

    dwt_kernel<<<NBC, 256>>>(x);
    attn_kernel<<<1, 32>>>(aw, ab);
    wino_mix<<<dim3(16, 4, 8), 256>>>(wt);
    wino_conv<<<dim3(32, 4, 8), 256, kConvSmem>>>();
    idwt_kernel<<<8192, 256>>>(out);
}